// round 11
// baseline (speedup 1.0000x reference)
#include <cuda_runtime.h>
#include <cstdint>

// ---------------------------------------------------------------------------
// TT embedding:  VOC = 100^3,  EMB = 4*4*8 = 128,  RANK = 16
//   out[tok, n1*32+n2*8+n3] = sum_{r1,r2} core0[i1,n1,r1]*core1[r1,i2,n2,r2]*core2[r2,i3,n3]
// idx = i1*10000 + i2*100 + i3; idx==0 (PAD) -> zero row.
//
// Kernel 1 : G01[i12][row*16+r2] = sum_r1 core0*core1  (10.2MB, L2-resident)
//            + fused pack of core2 into C2Q[i3][j][c][n3] (51KB), r2 = 4c+j.
//            A fetched 4-wide (LDS.128 broadcast) -> 36 LDS/thread vs 96.
// Kernel 2 : warp/token, minimal-wavefront layout (R9/R10 proven):
//   G: 2x contiguous LDG.128 (8 wf).  C: 8 instr, one 128B line each (8 wf),
//   address-permuted so reduce round 1 needs no selects.  2-round
//   reduce-scatter, 2x contiguous STG.64.  Reg cap 36 (7 blocks/SM).
// ---------------------------------------------------------------------------

#define VOC_LL 1000000ULL

__device__ float g_G01[10000 * 256];
__device__ float g_C2Q[100 * 128];   // [i3][j][c][n3] = core2[4c+j][i3][n3]

// ---- packed fp32x2 helpers (sm_103a) --------------------------------------
__device__ __forceinline__ unsigned long long f32x2_fma(
    unsigned long long a, unsigned long long b, unsigned long long c)
{
    unsigned long long d;
    asm("fma.rn.f32x2 %0, %1, %2, %3;" : "=l"(d) : "l"(a), "l"(b), "l"(c));
    return d;
}
__device__ __forceinline__ unsigned long long f32x2_add(
    unsigned long long a, unsigned long long b)
{
    unsigned long long d;
    asm("add.rn.f32x2 %0, %1, %2;" : "=l"(d) : "l"(a), "l"(b));
    return d;
}
__device__ __forceinline__ unsigned long long f32x2_bcast(float x)
{
    unsigned long long d;
    asm("mov.b64 %0, {%1, %1};" : "=l"(d) : "f"(x));
    return d;
}
__device__ __forceinline__ unsigned long long shfl_xor_u64(unsigned long long v, int m)
{
    unsigned int lo = (unsigned int)v, hi = (unsigned int)(v >> 32);
    lo = __shfl_xor_sync(0xffffffffu, lo, m);
    hi = __shfl_xor_sync(0xffffffffu, hi, m);
    return ((unsigned long long)hi << 32) | lo;
}

// ---------------------------------------------------------------------------
// Kernel 1: G01 precompute + fused core2 pack.
// grid = (100, 21), block = 128.
//   y < 20 : G01 for i2 = blockIdx.x, i1 in [5y, 5y+5)
//   y == 20: pack core2 for i3 = blockIdx.x
// core0: (1,100,4,16)  elem (i1,n1,r1)    @ i1*64 + n1*16 + r1
// core1: (16,100,4,16) elem (r1,i2,n2,r2) @ r1*6400 + i2*64 + n2*16 + r2
// core2: (16,100,8)    elem (r2,i3,n3)    @ r2*800 + i3*8 + n3
// ---------------------------------------------------------------------------
__global__ void __launch_bounds__(128) tt_precompute(
    const float* __restrict__ core0,
    const float* __restrict__ core1,
    const float* __restrict__ core2)
{
    const int i2 = blockIdx.x;
    const int g  = blockIdx.y;
    const int p  = threadIdx.x;

    if (g == 20) {
        // pack: C2Q[i3*128 + p],  p = j*32 + c*8 + n3,  r2 = 4c + j
        const int i3 = i2;
        const int j  = p >> 5;
        const int c  = (p >> 3) & 3;
        const int n3 = p & 7;
        g_C2Q[i3 * 128 + p] = core2[(4 * c + j) * 800 + i3 * 8 + n3];
        return;
    }

    __shared__ __align__(16) float Bs[1024]; // core1 slice: [r1][n2*16+r2]
    __shared__ __align__(16) float As[320];  // core0 slices 5 i1: [q][n1*16+r1]

    #pragma unroll
    for (int j = p; j < 1024; j += 128)
        Bs[j] = core1[(j >> 6) * 6400 + i2 * 64 + (j & 63)];
    #pragma unroll
    for (int j = p; j < 320; j += 128)
        As[j] = core0[g * 320 + j];
    __syncthreads();

    const int n1 = p >> 5;         // constant per warp -> As broadcast
    const int rp = (p & 31) * 2;   // rest pair start (n2*16+r2)

    unsigned long long b2[16];
    #pragma unroll
    for (int r1 = 0; r1 < 16; r1++)
        b2[r1] = *(const unsigned long long*)&Bs[r1 * 64 + rp];

    #pragma unroll
    for (int q = 0; q < 5; q++) {
        // A fetched 4-wide; two accumulator chains (depth 8 each)
        unsigned long long accE = 0, accO = 0;
        #pragma unroll
        for (int r4 = 0; r4 < 4; r4++) {
            const float4 av = *(const float4*)&As[q * 64 + n1 * 16 + r4 * 4];
            accE = f32x2_fma(f32x2_bcast(av.x), b2[r4 * 4 + 0], accE);
            accO = f32x2_fma(f32x2_bcast(av.y), b2[r4 * 4 + 1], accO);
            accE = f32x2_fma(f32x2_bcast(av.z), b2[r4 * 4 + 2], accE);
            accO = f32x2_fma(f32x2_bcast(av.w), b2[r4 * 4 + 3], accO);
        }
        const unsigned long long acc = f32x2_add(accE, accO);
        const int i1 = g * 5 + q;
        *(unsigned long long*)&g_G01[((size_t)(i1 * 100 + i2)) * 256 + p * 2] = acc;
    }
}

// ---------------------------------------------------------------------------
// Kernel 2: gather.  1 warp per token, 4 outputs/lane.
// lane L: k = L>>2 (rows k, k+8), c = L&3 (r2-quad [4c,4c+4)),
//         b1 = c&1 (n3-half kept), b2 = c>>1 (n3-pair kept within half).
// ---------------------------------------------------------------------------
__global__ void __launch_bounds__(256, 7) tt_gather(
    const void*  __restrict__ xraw,
    float*       __restrict__ out,
    int n_tok)
{
    const int t    = threadIdx.x;
    const int lane = t & 31;
    const int tok  = blockIdx.x * 8 + (t >> 5);
    if (tok >= n_tok) return;

    // --- index dtype autodetect: one 16B broadcast load, 2 samples.
    // int32 data misread as u64 is >= VOC unless the paired hi word is 0
    // (p ~ 1e-12 for both samples); int64 data is always < VOC.
    const ulonglong2 ds = *(const ulonglong2*)xraw;
    const bool is64 = (ds.x < VOC_LL) && (ds.y < VOC_LL);

    const long long idxll = is64 ? ((const long long*)xraw)[tok]
                                 : (long long)((const int*)xraw)[tok];
    const unsigned int iv  = (unsigned int)idxll;      // < 1e6
    const unsigned int i3  = iv % 100u;
    const unsigned int i12 = iv / 100u;

    const int k  = lane >> 2;
    const int c  = lane & 3;
    const int b1 = c & 1;
    const int b2 = (c >> 1) & 1;

    // G: 2 contiguous LDG.128 (512B each -> 4 lines per instruction)
    // ga = row k, r2 [4c,4c+4);  gb = row k+8, same quad.
    const float4* __restrict__ Gp = (const float4*)(g_G01 + (size_t)i12 * 256);
    const float4 ga = Gp[lane];
    const float4 gb = Gp[lane + 32];
    const float gA[4] = { ga.x, ga.y, ga.z, ga.w };
    const float gB[4] = { gb.x, gb.y, gb.z, gb.w };

    // C2Q, address-permuted: cb0 -> the n3-half this lane KEEPS (b1),
    // cb1 -> the half it will send.  Per instruction the warp still stays
    // inside one 128B line (permute only toggles +-16B within the line).
    const char* __restrict__ cbase =
        (const char*)g_C2Q + (size_t)i3 * 512 + c * 32;
    const char* cb0 = cbase + 16 * b1;
    const char* cb1 = cbase + 16 * (1 - b1);

    // partials: rows {k, k+8}; acc0/acc1 = kept half, acc2/acc3 = send half
    unsigned long long aA0 = 0, aA1 = 0, aA2 = 0, aA3 = 0;
    unsigned long long aB0 = 0, aB1 = 0, aB2 = 0, aB3 = 0;
    #pragma unroll
    for (int j = 0; j < 4; j++) {
        const ulonglong2 cK = *(const ulonglong2*)(cb0 + j * 128);  // kept half
        const ulonglong2 cS = *(const ulonglong2*)(cb1 + j * 128);  // send half
        const unsigned long long ggA = f32x2_bcast(gA[j]);
        const unsigned long long ggB = f32x2_bcast(gB[j]);
        aA0 = f32x2_fma(ggA, cK.x, aA0);
        aA1 = f32x2_fma(ggA, cK.y, aA1);
        aA2 = f32x2_fma(ggA, cS.x, aA2);
        aA3 = f32x2_fma(ggA, cS.y, aA3);
        aB0 = f32x2_fma(ggB, cK.x, aB0);
        aB1 = f32x2_fma(ggB, cK.y, aB1);
        aB2 = f32x2_fma(ggB, cS.x, aB2);
        aB3 = f32x2_fma(ggB, cS.y, aB3);
    }

    // round 1 (xor 1): partner's acc2/acc3 are MY half -> no selects.
    const unsigned long long k0A = f32x2_add(aA0, shfl_xor_u64(aA2, 1));
    const unsigned long long k1A = f32x2_add(aA1, shfl_xor_u64(aA3, 1));
    const unsigned long long k0B = f32x2_add(aB0, shfl_xor_u64(aB2, 1));
    const unsigned long long k1B = f32x2_add(aB1, shfl_xor_u64(aB3, 1));

    // round 2 (xor 2): keep pair 2b1+b2, send the other pair.
    const unsigned long long kkA = b2 ? k1A : k0A;
    const unsigned long long ssA = b2 ? k0A : k1A;
    const unsigned long long kkB = b2 ? k1B : k0B;
    const unsigned long long ssB = b2 ? k0B : k1B;
    unsigned long long fA = f32x2_add(kkA, shfl_xor_u64(ssA, 2));
    unsigned long long fB = f32x2_add(kkB, shfl_xor_u64(ssB, 2));

    if (iv == 0) { fA = 0; fB = 0; }   // PAD row

    // store: rows k and k+8, n3 pair starting at 4b1 + 2b2
    // (warp-wide: 2 stores, each covering a contiguous 256B half-row)
    const int n3off = 4 * b1 + 2 * b2;
    float* obase = out + (size_t)tok * 128;
    *(unsigned long long*)(obase + k * 8 + n3off)       = fA;
    *(unsigned long long*)(obase + (k + 8) * 8 + n3off) = fB;
}

// ---------------------------------------------------------------------------
extern "C" void kernel_launch(void* const* d_in, const int* in_sizes, int n_in,
                              void* d_out, int out_size)
{
    const void*  x     = d_in[0];
    const float* core0 = (const float*)d_in[1];
    const float* core1 = (const float*)d_in[2];
    const float* core2 = (const float*)d_in[3];
    float*       out   = (float*)d_out;

    const int n_tok = in_sizes[0];   // 32768

    tt_precompute<<<dim3(100, 21), 128>>>(core0, core1, core2);
    tt_gather<<<(n_tok + 7) / 8, 256>>>(x, out, n_tok);
}

// round 12
// speedup vs baseline: 1.1087x; 1.1087x over previous
#include <cuda_runtime.h>
#include <cstdint>

// ---------------------------------------------------------------------------
// TT embedding:  VOC = 100^3,  EMB = 4*4*8 = 128,  RANK = 16
//   out[tok, n1*32+n2*8+n3] = sum_{r1,r2} core0[i1,n1,r1]*core1[r1,i2,n2,r2]*core2[r2,i3,n3]
// idx = i1*10000 + i2*100 + i3; idx==0 (PAD) -> zero row.
//
// Kernel 1 : G01[i12][row*16+r2] = sum_r1 core0*core1  (10.2MB, L2-resident)
//            + fused pack of core2 into C2Q[i3][j][c][n3] (51KB), r2 = 4c+j.
//            A fetched 4-wide (LDS.128 broadcast) -> 36 LDS/thread vs 96.
// Kernel 2 : warp/token, minimal-wavefront layout (R10 exact):
//   G: 2x contiguous LDG.128 (8 wf).  C: 8 instr, one 128B line each (8 wf),
//   address-permuted so reduce round 1 needs no selects.  2-round
//   reduce-scatter, 2x contiguous STG.64.  Launch bounds (256,6): regs ~40,
//   which preserves ptxas load batching / per-warp MLP (caps of 7-8 blocks
//   clamp regs to 32 and regress 20-25% -- verified rounds 8 and 11).
// ---------------------------------------------------------------------------

#define VOC_LL 1000000ULL

__device__ float g_G01[10000 * 256];
__device__ float g_C2Q[100 * 128];   // [i3][j][c][n3] = core2[4c+j][i3][n3]

// ---- packed fp32x2 helpers (sm_103a) --------------------------------------
__device__ __forceinline__ unsigned long long f32x2_fma(
    unsigned long long a, unsigned long long b, unsigned long long c)
{
    unsigned long long d;
    asm("fma.rn.f32x2 %0, %1, %2, %3;" : "=l"(d) : "l"(a), "l"(b), "l"(c));
    return d;
}
__device__ __forceinline__ unsigned long long f32x2_add(
    unsigned long long a, unsigned long long b)
{
    unsigned long long d;
    asm("add.rn.f32x2 %0, %1, %2;" : "=l"(d) : "l"(a), "l"(b));
    return d;
}
__device__ __forceinline__ unsigned long long f32x2_bcast(float x)
{
    unsigned long long d;
    asm("mov.b64 %0, {%1, %1};" : "=l"(d) : "f"(x));
    return d;
}
__device__ __forceinline__ unsigned long long shfl_xor_u64(unsigned long long v, int m)
{
    unsigned int lo = (unsigned int)v, hi = (unsigned int)(v >> 32);
    lo = __shfl_xor_sync(0xffffffffu, lo, m);
    hi = __shfl_xor_sync(0xffffffffu, hi, m);
    return ((unsigned long long)hi << 32) | lo;
}

// ---------------------------------------------------------------------------
// Kernel 1: G01 precompute + fused core2 pack.
// grid = (100, 21), block = 128.
//   y < 20 : G01 for i2 = blockIdx.x, i1 in [5y, 5y+5)
//   y == 20: pack core2 for i3 = blockIdx.x
// core0: (1,100,4,16)  elem (i1,n1,r1)    @ i1*64 + n1*16 + r1
// core1: (16,100,4,16) elem (r1,i2,n2,r2) @ r1*6400 + i2*64 + n2*16 + r2
// core2: (16,100,8)    elem (r2,i3,n3)    @ r2*800 + i3*8 + n3
// ---------------------------------------------------------------------------
__global__ void __launch_bounds__(128) tt_precompute(
    const float* __restrict__ core0,
    const float* __restrict__ core1,
    const float* __restrict__ core2)
{
    const int i2 = blockIdx.x;
    const int g  = blockIdx.y;
    const int p  = threadIdx.x;

    if (g == 20) {
        // pack: C2Q[i3*128 + p],  p = j*32 + c*8 + n3,  r2 = 4c + j
        const int i3 = i2;
        const int j  = p >> 5;
        const int c  = (p >> 3) & 3;
        const int n3 = p & 7;
        g_C2Q[i3 * 128 + p] = core2[(4 * c + j) * 800 + i3 * 8 + n3];
        return;
    }

    __shared__ __align__(16) float Bs[1024]; // core1 slice: [r1][n2*16+r2]
    __shared__ __align__(16) float As[320];  // core0 slices 5 i1: [q][n1*16+r1]

    #pragma unroll
    for (int j = p; j < 1024; j += 128)
        Bs[j] = core1[(j >> 6) * 6400 + i2 * 64 + (j & 63)];
    #pragma unroll
    for (int j = p; j < 320; j += 128)
        As[j] = core0[g * 320 + j];
    __syncthreads();

    const int n1 = p >> 5;         // constant per warp -> As broadcast
    const int rp = (p & 31) * 2;   // rest pair start (n2*16+r2)

    unsigned long long b2[16];
    #pragma unroll
    for (int r1 = 0; r1 < 16; r1++)
        b2[r1] = *(const unsigned long long*)&Bs[r1 * 64 + rp];

    #pragma unroll
    for (int q = 0; q < 5; q++) {
        // A fetched 4-wide; two accumulator chains (depth 8 each)
        unsigned long long accE = 0, accO = 0;
        #pragma unroll
        for (int r4 = 0; r4 < 4; r4++) {
            const float4 av = *(const float4*)&As[q * 64 + n1 * 16 + r4 * 4];
            accE = f32x2_fma(f32x2_bcast(av.x), b2[r4 * 4 + 0], accE);
            accO = f32x2_fma(f32x2_bcast(av.y), b2[r4 * 4 + 1], accO);
            accE = f32x2_fma(f32x2_bcast(av.z), b2[r4 * 4 + 2], accE);
            accO = f32x2_fma(f32x2_bcast(av.w), b2[r4 * 4 + 3], accO);
        }
        const unsigned long long acc = f32x2_add(accE, accO);
        const int i1 = g * 5 + q;
        *(unsigned long long*)&g_G01[((size_t)(i1 * 100 + i2)) * 256 + p * 2] = acc;
    }
}

// ---------------------------------------------------------------------------
// Kernel 2: gather.  1 warp per token, 4 outputs/lane.  (R10 exact)
// lane L: k = L>>2 (rows k, k+8), c = L&3 (r2-quad [4c,4c+4)),
//         b1 = c&1 (n3-half kept), b2 = c>>1 (n3-pair kept within half).
// ---------------------------------------------------------------------------
__global__ void __launch_bounds__(256, 6) tt_gather(
    const void*  __restrict__ xraw,
    float*       __restrict__ out,
    int n_tok)
{
    const int t    = threadIdx.x;
    const int lane = t & 31;
    const int tok  = blockIdx.x * 8 + (t >> 5);
    if (tok >= n_tok) return;

    // --- index dtype autodetect: one 16B broadcast load, 2 samples.
    // int32 data misread as u64 is >= VOC unless the paired hi word is 0
    // (p ~ 1e-12 for both samples); int64 data is always < VOC.
    const ulonglong2 ds = *(const ulonglong2*)xraw;
    const bool is64 = (ds.x < VOC_LL) && (ds.y < VOC_LL);

    const long long idxll = is64 ? ((const long long*)xraw)[tok]
                                 : (long long)((const int*)xraw)[tok];
    const unsigned int iv  = (unsigned int)idxll;      // < 1e6
    const unsigned int i3  = iv % 100u;
    const unsigned int i12 = iv / 100u;

    const int k  = lane >> 2;
    const int c  = lane & 3;
    const int b1 = c & 1;
    const int b2 = (c >> 1) & 1;

    // G: 2 contiguous LDG.128 (512B each -> 4 lines per instruction)
    // ga = row k, r2 [4c,4c+4);  gb = row k+8, same quad.
    const float4* __restrict__ Gp = (const float4*)(g_G01 + (size_t)i12 * 256);
    const float4 ga = Gp[lane];
    const float4 gb = Gp[lane + 32];
    const float gA[4] = { ga.x, ga.y, ga.z, ga.w };
    const float gB[4] = { gb.x, gb.y, gb.z, gb.w };

    // C2Q, address-permuted: cb0 -> the n3-half this lane KEEPS (b1),
    // cb1 -> the half it will send.  Per instruction the warp still stays
    // inside one 128B line (permute only toggles +-16B within the line).
    const char* __restrict__ cbase =
        (const char*)g_C2Q + (size_t)i3 * 512 + c * 32;
    const char* cb0 = cbase + 16 * b1;
    const char* cb1 = cbase + 16 * (1 - b1);

    // partials: rows {k, k+8}; acc0/acc1 = kept half, acc2/acc3 = send half
    unsigned long long aA0 = 0, aA1 = 0, aA2 = 0, aA3 = 0;
    unsigned long long aB0 = 0, aB1 = 0, aB2 = 0, aB3 = 0;
    #pragma unroll
    for (int j = 0; j < 4; j++) {
        const ulonglong2 cK = *(const ulonglong2*)(cb0 + j * 128);  // kept half
        const ulonglong2 cS = *(const ulonglong2*)(cb1 + j * 128);  // send half
        const unsigned long long ggA = f32x2_bcast(gA[j]);
        const unsigned long long ggB = f32x2_bcast(gB[j]);
        aA0 = f32x2_fma(ggA, cK.x, aA0);
        aA1 = f32x2_fma(ggA, cK.y, aA1);
        aA2 = f32x2_fma(ggA, cS.x, aA2);
        aA3 = f32x2_fma(ggA, cS.y, aA3);
        aB0 = f32x2_fma(ggB, cK.x, aB0);
        aB1 = f32x2_fma(ggB, cK.y, aB1);
        aB2 = f32x2_fma(ggB, cS.x, aB2);
        aB3 = f32x2_fma(ggB, cS.y, aB3);
    }

    // round 1 (xor 1): partner's acc2/acc3 are MY half -> no selects.
    const unsigned long long k0A = f32x2_add(aA0, shfl_xor_u64(aA2, 1));
    const unsigned long long k1A = f32x2_add(aA1, shfl_xor_u64(aA3, 1));
    const unsigned long long k0B = f32x2_add(aB0, shfl_xor_u64(aB2, 1));
    const unsigned long long k1B = f32x2_add(aB1, shfl_xor_u64(aB3, 1));

    // round 2 (xor 2): keep pair 2b1+b2, send the other pair.
    const unsigned long long kkA = b2 ? k1A : k0A;
    const unsigned long long ssA = b2 ? k0A : k1A;
    const unsigned long long kkB = b2 ? k1B : k0B;
    const unsigned long long ssB = b2 ? k0B : k1B;
    unsigned long long fA = f32x2_add(kkA, shfl_xor_u64(ssA, 2));
    unsigned long long fB = f32x2_add(kkB, shfl_xor_u64(ssB, 2));

    if (iv == 0) { fA = 0; fB = 0; }   // PAD row

    // store: rows k and k+8, n3 pair starting at 4b1 + 2b2
    // (warp-wide: 2 stores, each covering a contiguous 256B half-row)
    const int n3off = 4 * b1 + 2 * b2;
    float* obase = out + (size_t)tok * 128;
    *(unsigned long long*)(obase + k * 8 + n3off)       = fA;
    *(unsigned long long*)(obase + (k + 8) * 8 + n3off) = fB;
}

// ---------------------------------------------------------------------------
extern "C" void kernel_launch(void* const* d_in, const int* in_sizes, int n_in,
                              void* d_out, int out_size)
{
    const void*  x     = d_in[0];
    const float* core0 = (const float*)d_in[1];
    const float* core1 = (const float*)d_in[2];
    const float* core2 = (const float*)d_in[3];
    float*       out   = (float*)d_out;

    const int n_tok = in_sizes[0];   // 32768

    tt_precompute<<<dim3(100, 21), 128>>>(core0, core1, core2);
    tt_gather<<<(n_tok + 7) / 8, 256>>>(x, out, n_tok);
}

// round 13
// speedup vs baseline: 1.1199x; 1.0101x over previous
#include <cuda_runtime.h>
#include <cstdint>

// ---------------------------------------------------------------------------
// TT embedding:  VOC = 100^3,  EMB = 4*4*8 = 128,  RANK = 16
//   out[tok, n1*32+n2*8+n3] = sum_{r1,r2} core0[i1,n1,r1]*core1[r1,i2,n2,r2]*core2[r2,i3,n3]
// idx = i1*10000 + i2*100 + i3; idx==0 (PAD) -> zero row.
//
// Kernel 1 : G01[i12][row*16+r2] = sum_r1 core0*core1  (10.2MB, L2-resident)
//            + fused pack of core2 into C2Q (51KB), r2 = 4c+j.
//            NO shared memory: b2 column loaded straight from gmem (L2-hot,
//            reused 10x), A rows via warp-uniform LDG.128 broadcast.
// Kernel 2 : warp/token, minimal-wavefront layout (R10/R12 frozen):
//   G: 2x contiguous LDG.128 (8 wf).  C: 8 instr, one 128B line each (8 wf),
//   address-permuted so reduce round 1 needs no selects.  2-round
//   reduce-scatter, 2x contiguous STG.64.  Launch bounds (256,6): regs ~40
//   (caps forcing 32 regs kill ptxas load batching -- verified R8, R11).
// ---------------------------------------------------------------------------

#define VOC_LL 1000000ULL

__device__ float g_G01[10000 * 256];
__device__ float g_C2Q[100 * 128];   // [i3][j][c][n3] = core2[4c+j][i3][n3]

// ---- packed fp32x2 helpers (sm_103a) --------------------------------------
__device__ __forceinline__ unsigned long long f32x2_fma(
    unsigned long long a, unsigned long long b, unsigned long long c)
{
    unsigned long long d;
    asm("fma.rn.f32x2 %0, %1, %2, %3;" : "=l"(d) : "l"(a), "l"(b), "l"(c));
    return d;
}
__device__ __forceinline__ unsigned long long f32x2_add(
    unsigned long long a, unsigned long long b)
{
    unsigned long long d;
    asm("add.rn.f32x2 %0, %1, %2;" : "=l"(d) : "l"(a), "l"(b));
    return d;
}
__device__ __forceinline__ unsigned long long f32x2_bcast(float x)
{
    unsigned long long d;
    asm("mov.b64 %0, {%1, %1};" : "=l"(d) : "f"(x));
    return d;
}
__device__ __forceinline__ unsigned long long shfl_xor_u64(unsigned long long v, int m)
{
    unsigned int lo = (unsigned int)v, hi = (unsigned int)(v >> 32);
    lo = __shfl_xor_sync(0xffffffffu, lo, m);
    hi = __shfl_xor_sync(0xffffffffu, hi, m);
    return ((unsigned long long)hi << 32) | lo;
}

// ---------------------------------------------------------------------------
// Kernel 1: G01 precompute + fused core2 pack.  NO SMEM.
// grid = (100, 11), block = 128.
//   y < 10 : G01 for i2 = blockIdx.x, i1 in [10y, 10y+10)
//   y == 10: pack core2 for i3 = blockIdx.x
// core0: (1,100,4,16)  elem (i1,n1,r1)    @ i1*64 + n1*16 + r1
// core1: (16,100,4,16) elem (r1,i2,n2,r2) @ r1*6400 + i2*64 + n2*16 + r2
// core2: (16,100,8)    elem (r2,i3,n3)    @ r2*800 + i3*8 + n3
// ---------------------------------------------------------------------------
__global__ void __launch_bounds__(128) tt_precompute(
    const float* __restrict__ core0,
    const float* __restrict__ core1,
    const float* __restrict__ core2)
{
    const int i2 = blockIdx.x;
    const int g  = blockIdx.y;
    const int p  = threadIdx.x;

    if (g == 10) {
        // pack: C2Q[i3*128 + p],  p = j*32 + c*8 + n3,  r2 = 4c + j
        const int i3 = i2;
        const int j  = p >> 5;
        const int c  = (p >> 3) & 3;
        const int n3 = p & 7;
        g_C2Q[i3 * 128 + p] = core2[(4 * c + j) * 800 + i3 * 8 + n3];
        return;
    }

    const int n1 = p >> 5;         // constant per warp
    const int rp = (p & 31) * 2;   // rest pair start (n2*16+r2)

    // B column straight from gmem (core1 = 400KB, L2-resident; each LDG.64
    // covers 256B across the warp).  Reused for 10 i1's.
    unsigned long long b2[16];
    #pragma unroll
    for (int r1 = 0; r1 < 16; r1++)
        b2[r1] = *(const unsigned long long*)&core1[r1 * 6400 + i2 * 64 + rp];

    const float* __restrict__ a0 = core0 + (size_t)g * 640 + n1 * 16;

    #pragma unroll
    for (int q = 0; q < 10; q++) {
        // A row fetched 4-wide, warp-uniform (broadcast, L1-hot)
        unsigned long long accE = 0, accO = 0;
        #pragma unroll
        for (int r4 = 0; r4 < 4; r4++) {
            const float4 av = *(const float4*)(a0 + q * 64 + r4 * 4);
            accE = f32x2_fma(f32x2_bcast(av.x), b2[r4 * 4 + 0], accE);
            accO = f32x2_fma(f32x2_bcast(av.y), b2[r4 * 4 + 1], accO);
            accE = f32x2_fma(f32x2_bcast(av.z), b2[r4 * 4 + 2], accE);
            accO = f32x2_fma(f32x2_bcast(av.w), b2[r4 * 4 + 3], accO);
        }
        const unsigned long long acc = f32x2_add(accE, accO);
        const int i1 = g * 10 + q;
        *(unsigned long long*)&g_G01[((size_t)(i1 * 100 + i2)) * 256 + p * 2] = acc;
    }
}

// ---------------------------------------------------------------------------
// Kernel 2: gather.  1 warp per token, 4 outputs/lane.  (R10/R12 frozen)
// lane L: k = L>>2 (rows k, k+8), c = L&3 (r2-quad [4c,4c+4)),
//         b1 = c&1 (n3-half kept), b2 = c>>1 (n3-pair kept within half).
// ---------------------------------------------------------------------------
__global__ void __launch_bounds__(256, 6) tt_gather(
    const void*  __restrict__ xraw,
    float*       __restrict__ out,
    int n_tok)
{
    const int t    = threadIdx.x;
    const int lane = t & 31;
    const int tok  = blockIdx.x * 8 + (t >> 5);
    if (tok >= n_tok) return;

    // --- index dtype autodetect: one 16B broadcast load, 2 samples.
    // int32 data misread as u64 is >= VOC unless the paired hi word is 0
    // (p ~ 1e-12 for both samples); int64 data is always < VOC.
    const ulonglong2 ds = *(const ulonglong2*)xraw;
    const bool is64 = (ds.x < VOC_LL) && (ds.y < VOC_LL);

    const long long idxll = is64 ? ((const long long*)xraw)[tok]
                                 : (long long)((const int*)xraw)[tok];
    const unsigned int iv  = (unsigned int)idxll;      // < 1e6
    const unsigned int i3  = iv % 100u;
    const unsigned int i12 = iv / 100u;

    const int k  = lane >> 2;
    const int c  = lane & 3;
    const int b1 = c & 1;
    const int b2 = (c >> 1) & 1;

    // G: 2 contiguous LDG.128 (512B each -> 4 lines per instruction)
    // ga = row k, r2 [4c,4c+4);  gb = row k+8, same quad.
    const float4* __restrict__ Gp = (const float4*)(g_G01 + (size_t)i12 * 256);
    const float4 ga = Gp[lane];
    const float4 gb = Gp[lane + 32];
    const float gA[4] = { ga.x, ga.y, ga.z, ga.w };
    const float gB[4] = { gb.x, gb.y, gb.z, gb.w };

    // C2Q, address-permuted: cb0 -> the n3-half this lane KEEPS (b1),
    // cb1 -> the half it will send.  Per instruction the warp still stays
    // inside one 128B line (permute only toggles +-16B within the line).
    const char* __restrict__ cbase =
        (const char*)g_C2Q + (size_t)i3 * 512 + c * 32;
    const char* cb0 = cbase + 16 * b1;
    const char* cb1 = cbase + 16 * (1 - b1);

    // partials: rows {k, k+8}; acc0/acc1 = kept half, acc2/acc3 = send half
    unsigned long long aA0 = 0, aA1 = 0, aA2 = 0, aA3 = 0;
    unsigned long long aB0 = 0, aB1 = 0, aB2 = 0, aB3 = 0;
    #pragma unroll
    for (int j = 0; j < 4; j++) {
        const ulonglong2 cK = *(const ulonglong2*)(cb0 + j * 128);  // kept half
        const ulonglong2 cS = *(const ulonglong2*)(cb1 + j * 128);  // send half
        const unsigned long long ggA = f32x2_bcast(gA[j]);
        const unsigned long long ggB = f32x2_bcast(gB[j]);
        aA0 = f32x2_fma(ggA, cK.x, aA0);
        aA1 = f32x2_fma(ggA, cK.y, aA1);
        aA2 = f32x2_fma(ggA, cS.x, aA2);
        aA3 = f32x2_fma(ggA, cS.y, aA3);
        aB0 = f32x2_fma(ggB, cK.x, aB0);
        aB1 = f32x2_fma(ggB, cK.y, aB1);
        aB2 = f32x2_fma(ggB, cS.x, aB2);
        aB3 = f32x2_fma(ggB, cS.y, aB3);
    }

    // round 1 (xor 1): partner's acc2/acc3 are MY half -> no selects.
    const unsigned long long k0A = f32x2_add(aA0, shfl_xor_u64(aA2, 1));
    const unsigned long long k1A = f32x2_add(aA1, shfl_xor_u64(aA3, 1));
    const unsigned long long k0B = f32x2_add(aB0, shfl_xor_u64(aB2, 1));
    const unsigned long long k1B = f32x2_add(aB1, shfl_xor_u64(aB3, 1));

    // round 2 (xor 2): keep pair 2b1+b2, send the other pair.
    const unsigned long long kkA = b2 ? k1A : k0A;
    const unsigned long long ssA = b2 ? k0A : k1A;
    const unsigned long long kkB = b2 ? k1B : k0B;
    const unsigned long long ssB = b2 ? k0B : k1B;
    unsigned long long fA = f32x2_add(kkA, shfl_xor_u64(ssA, 2));
    unsigned long long fB = f32x2_add(kkB, shfl_xor_u64(ssB, 2));

    if (iv == 0) { fA = 0; fB = 0; }   // PAD row

    // store: rows k and k+8, n3 pair starting at 4b1 + 2b2
    // (warp-wide: 2 stores, each covering a contiguous 256B half-row)
    const int n3off = 4 * b1 + 2 * b2;
    float* obase = out + (size_t)tok * 128;
    *(unsigned long long*)(obase + k * 8 + n3off)       = fA;
    *(unsigned long long*)(obase + (k + 8) * 8 + n3off) = fB;
}

// ---------------------------------------------------------------------------
extern "C" void kernel_launch(void* const* d_in, const int* in_sizes, int n_in,
                              void* d_out, int out_size)
{
    const void*  x     = d_in[0];
    const float* core0 = (const float*)d_in[1];
    const float* core1 = (const float*)d_in[2];
    const float* core2 = (const float*)d_in[3];
    float*       out   = (float*)d_out;

    const int n_tok = in_sizes[0];   // 32768

    tt_precompute<<<dim3(100, 11), 128>>>(core0, core1, core2);
    tt_gather<<<(n_tok + 7) / 8, 256>>>(x, out, n_tok);
}